// round 1
// baseline (speedup 1.0000x reference)
#include <cuda_runtime.h>
#include <math.h>

#define VOL    110592   // 48*48*48
#define PLANE  2304     // 48*48
#define NM     16       // 2 signs * B(2) * C(4)
#define NVOX   221184   // B * VOL
#define TOTALE 884736   // B*C*VOL
#define INF9   1.0e9f

// Static scratch (no allocations allowed)
__device__ float  g_bufA[NM * VOL];
__device__ float  g_bufB[NM * VOL];
__device__ int    g_flags[8];
__device__ int    g_is64;
__device__ double g_partials[256];

// ---------------------------------------------------------------------------
// Detect target dtype (int64 vs int32) + zero flags.
// If the buffer really holds int64 values in [0,3], every 8-byte read is in
// [0,3]. If it holds int32, an int64 read combines two values; the high word
// being 0 for 1024 consecutive odd entries has probability ~0.25^1024.
// ---------------------------------------------------------------------------
__global__ void k_detect(const void* __restrict__ target) {
    __shared__ int bad;
    if (threadIdx.x == 0) bad = 0;
    __syncthreads();
    const long long* t64 = (const long long*)target;
    for (int i = threadIdx.x; i < 1024; i += 256) {
        long long v = t64[i];
        if (v < 0 || v > 3) atomicOr(&bad, 1);
    }
    __syncthreads();
    if (threadIdx.x == 0) {
        g_is64 = bad ? 0 : 1;
        #pragma unroll
        for (int i = 0; i < 8; i++) g_flags[i] = 0;
    }
}

// ---------------------------------------------------------------------------
// Build pos/neg INF-masks and per-(b,c) presence flags.
// ---------------------------------------------------------------------------
__global__ void k_init(const void* __restrict__ target) {
    __shared__ int sf[8];
    if (threadIdx.x < 8) sf[threadIdx.x] = 0;
    __syncthreads();
    int idx = blockIdx.x * blockDim.x + threadIdx.x;
    if (idx < NVOX) {
        int b  = idx / VOL;
        int sp = idx - b * VOL;
        int t;
        if (g_is64) t = (int)((const long long*)target)[idx];
        else        t = ((const int*)target)[idx];
        #pragma unroll
        for (int c = 0; c < 4; c++) {
            bool p = (t == c);
            g_bufA[(b * 4 + c) * VOL + sp]     = p ? 0.0f : INF9;
            g_bufA[(8 + b * 4 + c) * VOL + sp] = p ? INF9 : 0.0f;
        }
        atomicOr(&sf[b * 4 + t], 1);
    }
    __syncthreads();
    if (threadIdx.x < 8 && sf[threadIdx.x]) atomicOr(&g_flags[threadIdx.x], 1);
}

// ---------------------------------------------------------------------------
// One exact 1D min-plus pass over one axis of every 48x48 plane.
// AX==0: reduce along W (plane = (h,w) at fixed (m,d))
// AX==1: reduce along H (plane = (h,w) at fixed (m,d))
// AX==2: reduce along D (plane = (d,w) at fixed (m,h))
// Uses f[j]+(x-j)^2 = (f[j]+j^2) + (-2j)*x + x^2, exact in fp32 for all
// finite (integer, <2^24) values.
// SRCB: read g_bufB/write g_bufA if true, else A->B.
// 192 threads: lane = tid/4 in [0,48), group = tid%4 owns 12 outputs.
// ---------------------------------------------------------------------------
template <int AX, bool SRCB>
__global__ void __launch_bounds__(192) k_pass() {
    const float* __restrict__ in  = SRCB ? g_bufB : g_bufA;
    float*       __restrict__ out = SRCB ? g_bufA : g_bufB;

    __shared__ float s[48][49];

    int m = blockIdx.x / 48;
    int q = blockIdx.x - m * 48;
    int tid = threadIdx.x;

    int base_mq = (AX == 2) ? (m * VOL + q * 48) : (m * VOL + q * PLANE);

    // Load plane, folding +j^2 (j = reduction coordinate) into shared values.
    for (int i = tid; i < PLANE; i += 192) {
        int r = i / 48, c = i - r * 48;
        int addr = (AX == 2) ? (base_mq + r * PLANE + c) : (base_mq + i);
        float v = in[addr];
        int j = (AX == 0) ? c : r;
        s[r][c] = v + (float)(j * j);
    }
    __syncthreads();

    int grp  = tid & 3;
    int lane = tid >> 2;
    float x0 = (float)(grp * 12);

    float acc[12];
    #pragma unroll
    for (int k = 0; k < 12; k++) acc[k] = 1.0e30f;

    #pragma unroll
    for (int j = 0; j < 48; j++) {
        float sj = (AX == 0) ? s[lane][j] : s[j][lane];
        float cj = -2.0f * (float)j;
        #pragma unroll
        for (int k = 0; k < 12; k++) {
            acc[k] = fminf(acc[k], fmaf(cj, x0 + (float)k, sj));
        }
    }

    #pragma unroll
    for (int k = 0; k < 12; k++) {
        int x = grp * 12 + k;
        float val = acc[k] + (float)(x * x);
        int addr;
        if (AX == 0)      addr = base_mq + lane * 48 + x;   // (h=lane, w=x)
        else if (AX == 1) addr = base_mq + x * 48 + lane;   // (h=x, w=lane)
        else              addr = base_mq + x * PLANE + lane;// (d=x, w=lane)
        out[addr] = val;
    }
}

// ---------------------------------------------------------------------------
// Softmax + |p * sdf| partial sums (deterministic per-block doubles).
// Squared distances are in g_bufB after the three passes.
// ---------------------------------------------------------------------------
__global__ void __launch_bounds__(256) k_loss(const float* __restrict__ pred) {
    double sum = 0.0;
    int stride = gridDim.x * blockDim.x;
    for (int idx = blockIdx.x * blockDim.x + threadIdx.x; idx < NVOX; idx += stride) {
        int b  = idx / VOL;
        int sp = idx - b * VOL;
        int pb = b * 4 * VOL + sp;

        float p0 = pred[pb];
        float p1 = pred[pb + VOL];
        float p2 = pred[pb + 2 * VOL];
        float p3 = pred[pb + 3 * VOL];
        float mx = fmaxf(fmaxf(p0, p1), fmaxf(p2, p3));
        float e0 = expf(p0 - mx);
        float e1 = expf(p1 - mx);
        float e2 = expf(p2 - mx);
        float e3 = expf(p3 - mx);
        float inv = 1.0f / (e0 + e1 + e2 + e3);
        float e[4] = {e0, e1, e2, e3};

        float local = 0.0f;
        #pragma unroll
        for (int c = 0; c < 4; c++) {
            if (g_flags[b * 4 + c]) {
                float pos = g_bufB[(b * 4 + c) * VOL + sp];
                float neg = g_bufB[(8 + b * 4 + c) * VOL + sp];
                float sdf = sqrtf(pos) - sqrtf(neg);
                local += e[c] * fabsf(sdf);
            }
        }
        sum += (double)(local * inv);
    }

    __shared__ double sh[256];
    sh[threadIdx.x] = sum;
    __syncthreads();
    #pragma unroll
    for (int s = 128; s > 0; s >>= 1) {
        if (threadIdx.x < s) sh[threadIdx.x] += sh[threadIdx.x + s];
        __syncthreads();
    }
    if (threadIdx.x == 0) g_partials[blockIdx.x] = sh[0];
}

__global__ void k_finish(float* __restrict__ out) {
    __shared__ double sh[256];
    sh[threadIdx.x] = g_partials[threadIdx.x];
    __syncthreads();
    #pragma unroll
    for (int s = 128; s > 0; s >>= 1) {
        if (threadIdx.x < s) sh[threadIdx.x] += sh[threadIdx.x + s];
        __syncthreads();
    }
    if (threadIdx.x == 0) out[0] = (float)(sh[0] / (double)TOTALE);
}

// ---------------------------------------------------------------------------
extern "C" void kernel_launch(void* const* d_in, const int* in_sizes, int n_in,
                              void* d_out, int out_size) {
    const float* pred   = (const float*)d_in[0];
    const void*  target = d_in[1];
    float* out = (float*)d_out;

    k_detect<<<1, 256>>>(target);
    k_init<<<(NVOX + 255) / 256, 256>>>(target);

    k_pass<0, false><<<NM * 48, 192>>>();  // A -> B (W axis)
    k_pass<1, true ><<<NM * 48, 192>>>();  // B -> A (H axis)
    k_pass<2, false><<<NM * 48, 192>>>();  // A -> B (D axis)

    k_loss<<<256, 256>>>(pred);
    k_finish<<<1, 256>>>(out);
}

// round 2
// speedup vs baseline: 1.2250x; 1.2250x over previous
#include <cuda_runtime.h>
#include <math.h>

#define VOL    110592   // 48*48*48
#define PLANE  2304     // 48*48
#define NM     16       // 2 signs * B(2) * C(4); m = sign*8 + b*4 + c
#define NVOX   221184   // B * VOL
#define TOTALE 884736   // B*C*VOL
#define INF9   1.0e9f
#define LOSSBLKS 256

// Static scratch (no allocations allowed)
__device__ float  g_bufA[NM * VOL];
__device__ float  g_bufB[NM * VOL];
__device__ int    g_flags[8];
__device__ int    g_is64;
__device__ int    g_count;
__device__ double g_partials[LOSSBLKS];

// ---------------------------------------------------------------------------
// Detect target dtype (int64 vs int32); zero flags + completion counter.
// ---------------------------------------------------------------------------
__global__ void k_detect(const void* __restrict__ target) {
    __shared__ int bad;
    if (threadIdx.x == 0) bad = 0;
    __syncthreads();
    const long long* t64 = (const long long*)target;
    for (int i = threadIdx.x; i < 1024; i += 256) {
        long long v = t64[i];
        if (v < 0 || v > 3) atomicOr(&bad, 1);
    }
    __syncthreads();
    if (threadIdx.x == 0) {
        g_is64 = bad ? 0 : 1;
        g_count = 0;
        #pragma unroll
        for (int i = 0; i < 8; i++) g_flags[i] = 0;
    }
}

// ---------------------------------------------------------------------------
// Kernel A: fused one-hot init + exact W-EDT (bit-scan on 48-bit line masks)
// + exact H min-plus. One block per (m, d) plane. Writes squared dists (after
// W+H) to g_bufA in standard (d,h,w) layout.
// ---------------------------------------------------------------------------
__global__ void __launch_bounds__(192) kA(const void* __restrict__ target) {
    __shared__ unsigned char lab[PLANE];
    __shared__ unsigned long long lmask[48];
    __shared__ float s[48][49];
    __shared__ int anyflag;

    const int tid = threadIdx.x;
    const int m = blockIdx.x / 48;
    const int d = blockIdx.x - m * 48;
    const int sign = m >> 3;
    const int b = (m >> 2) & 1;
    const int c = m & 3;

    if (tid < 48) lmask[tid] = 0ULL;
    if (tid == 0) anyflag = 0;

    // Phase 0: load target plane labels into smem (coalesced).
    const int vbase = b * VOL + d * PLANE;
    if (g_is64) {
        const long long* t = (const long long*)target;
        for (int i = tid; i < PLANE; i += 192) lab[i] = (unsigned char)t[vbase + i];
    } else {
        const int* t = (const int*)target;
        for (int i = tid; i < PLANE; i += 192) lab[i] = (unsigned char)t[vbase + i];
    }
    __syncthreads();

    // Phase 1: build per-line seed bitmasks (thread owns 12 consecutive w of one line).
    {
        int h = tid >> 2;
        int w0 = (tid & 3) * 12;
        unsigned long long bits = 0ULL;
        int any = 0;
        #pragma unroll
        for (int k = 0; k < 12; k++) {
            int w = w0 + k;
            int isc = (lab[h * 48 + w] == (unsigned char)c);
            any |= isc;
            unsigned long long bin = (unsigned long long)(isc ^ sign);
            bits |= bin << w;
        }
        if (bits) atomicOr(&lmask[h], bits);
        if (any) anyflag = 1;
    }
    __syncthreads();

    if (tid == 0 && sign == 0 && anyflag) atomicOr(&g_flags[b * 4 + c], 1);

    // Phase 2: exact W distances via clz/ffs; fold +h^2 for the H pass.
    #pragma unroll
    for (int k = 0; k < 12; k++) {
        int i = tid + k * 192;
        int hh = i / 48;
        int ww = i - hh * 48;
        unsigned long long mm = lmask[hh];
        unsigned long long lowm = mm << (63 - ww);   // bits <= ww, msb-aligned
        unsigned long long him  = mm >> ww;          // bits >= ww
        int dl = lowm ? __clzll(lowm) : 99;
        int dr = him ? (__ffsll(him) - 1) : 99;
        int dd = min(dl, dr);
        float v = (dd <= 47) ? (float)(dd * dd) : INF9;
        s[hh][ww] = v + (float)(hh * hh);
    }
    __syncthreads();

    // Phase 3: H min-plus. grp owns 12 outputs x; lane = w.
    const int grp = tid & 3;
    const int lane = tid >> 2;
    float acc[12], xv[12];
    #pragma unroll
    for (int k = 0; k < 12; k++) { acc[k] = 1.0e30f; xv[k] = (float)(grp * 12 + k); }

    #pragma unroll
    for (int jc = 0; jc < 4; jc++) {
        float sv[12];
        #pragma unroll
        for (int t = 0; t < 12; t++) sv[t] = s[jc * 12 + t][lane];
        #pragma unroll
        for (int t = 0; t < 12; t++) {
            const float cj = -2.0f * (float)(jc * 12 + t);
            #pragma unroll
            for (int k = 0; k < 12; k++)
                acc[k] = fminf(acc[k], fmaf(cj, xv[k], sv[t]));
        }
    }

    const int base = m * VOL + d * PLANE;
    #pragma unroll
    for (int k = 0; k < 12; k++) {
        int x = grp * 12 + k;
        g_bufA[base + x * 48 + lane] = acc[k] + (float)(x * x);
    }
}

// ---------------------------------------------------------------------------
// Kernel B: exact D min-plus. One block per (m, h) plane (d, w).
// ---------------------------------------------------------------------------
__global__ void __launch_bounds__(192) kB() {
    __shared__ float s[48][49];
    const int tid = threadIdx.x;
    const int m = blockIdx.x / 48;
    const int h = blockIdx.x - m * 48;
    const int base = m * VOL + h * 48;

    for (int i = tid; i < PLANE; i += 192) {
        int dd = i / 48;
        int w = i - dd * 48;
        s[dd][w] = g_bufA[base + dd * PLANE + w] + (float)(dd * dd);
    }
    __syncthreads();

    const int grp = tid & 3;
    const int lane = tid >> 2;
    float acc[12], xv[12];
    #pragma unroll
    for (int k = 0; k < 12; k++) { acc[k] = 1.0e30f; xv[k] = (float)(grp * 12 + k); }

    #pragma unroll
    for (int jc = 0; jc < 4; jc++) {
        float sv[12];
        #pragma unroll
        for (int t = 0; t < 12; t++) sv[t] = s[jc * 12 + t][lane];
        #pragma unroll
        for (int t = 0; t < 12; t++) {
            const float cj = -2.0f * (float)(jc * 12 + t);
            #pragma unroll
            for (int k = 0; k < 12; k++)
                acc[k] = fminf(acc[k], fmaf(cj, xv[k], sv[t]));
        }
    }

    #pragma unroll
    for (int k = 0; k < 12; k++) {
        int x = grp * 12 + k;
        g_bufB[base + x * PLANE + lane] = acc[k] + (float)(x * x);
    }
}

// ---------------------------------------------------------------------------
// Loss: softmax + sum |p * sdf|, deterministic per-block double partials,
// last-finished block does the final reduction (saves a launch).
// ---------------------------------------------------------------------------
__global__ void __launch_bounds__(256) k_loss(const float* __restrict__ pred,
                                              float* __restrict__ out) {
    double sum = 0.0;
    const int stride = gridDim.x * blockDim.x;
    for (int idx = blockIdx.x * blockDim.x + threadIdx.x; idx < NVOX; idx += stride) {
        int b  = idx / VOL;
        int sp = idx - b * VOL;
        int pb = b * 4 * VOL + sp;

        float p0 = pred[pb];
        float p1 = pred[pb + VOL];
        float p2 = pred[pb + 2 * VOL];
        float p3 = pred[pb + 3 * VOL];
        float mx = fmaxf(fmaxf(p0, p1), fmaxf(p2, p3));
        float e[4];
        e[0] = __expf(p0 - mx);
        e[1] = __expf(p1 - mx);
        e[2] = __expf(p2 - mx);
        e[3] = __expf(p3 - mx);
        float inv = __fdividef(1.0f, e[0] + e[1] + e[2] + e[3]);

        float local = 0.0f;
        #pragma unroll
        for (int c = 0; c < 4; c++) {
            if (g_flags[b * 4 + c]) {
                float pos = g_bufB[(b * 4 + c) * VOL + sp];
                float neg = g_bufB[(8 + b * 4 + c) * VOL + sp];
                float sdf = sqrtf(pos) - sqrtf(neg);
                local += e[c] * fabsf(sdf);
            }
        }
        sum += (double)(local * inv);
    }

    __shared__ double sh[256];
    __shared__ int islast;
    sh[threadIdx.x] = sum;
    __syncthreads();
    #pragma unroll
    for (int s = 128; s > 0; s >>= 1) {
        if (threadIdx.x < s) sh[threadIdx.x] += sh[threadIdx.x + s];
        __syncthreads();
    }
    if (threadIdx.x == 0) {
        g_partials[blockIdx.x] = sh[0];
        __threadfence();
        int done = atomicAdd(&g_count, 1);
        islast = (done == gridDim.x - 1);
    }
    __syncthreads();

    if (islast) {
        sh[threadIdx.x] = g_partials[threadIdx.x];
        __syncthreads();
        #pragma unroll
        for (int s = 128; s > 0; s >>= 1) {
            if (threadIdx.x < s) sh[threadIdx.x] += sh[threadIdx.x + s];
            __syncthreads();
        }
        if (threadIdx.x == 0) out[0] = (float)(sh[0] / (double)TOTALE);
    }
}

// ---------------------------------------------------------------------------
extern "C" void kernel_launch(void* const* d_in, const int* in_sizes, int n_in,
                              void* d_out, int out_size) {
    const float* pred   = (const float*)d_in[0];
    const void*  target = d_in[1];
    float* out = (float*)d_out;

    k_detect<<<1, 256>>>(target);
    kA<<<NM * 48, 192>>>(target);   // init + W (bit-scan) + H (min-plus) -> g_bufA
    kB<<<NM * 48, 192>>>();         // D (min-plus) -> g_bufB
    k_loss<<<LOSSBLKS, 256>>>(pred, out);
}

// round 3
// speedup vs baseline: 1.2833x; 1.0476x over previous
#include <cuda_runtime.h>
#include <math.h>

#define VOL    110592   // 48*48*48
#define PLANE  2304     // 48*48
#define NM     16       // 2 signs * B(2) * C(4); m = sign*8 + b*4 + c
#define NVOX   221184   // B * VOL
#define TOTALE 884736   // B*C*VOL
#define INF9   1.0e9f
#define LUTN   6640
#define LOSSBLKS 864    // NVOX / 256

// Static scratch (no allocations allowed)
__device__ float  g_bufA[NM * VOL];
__device__ float  g_bufB[8 * VOL];    // summed pos^2+neg^2 per (b,c)
__device__ float  g_lut[LUTN];
__device__ int    g_flags[8];
__device__ int    g_is64;
__device__ int    g_count;
__device__ double g_partials[LOSSBLKS];

// ---------------------------------------------------------------------------
// Detect target dtype (int64 vs int32); zero flags/counter; build sqrt LUT.
// ---------------------------------------------------------------------------
__global__ void k_detect(const void* __restrict__ target) {
    __shared__ int bad;
    if (threadIdx.x == 0) bad = 0;
    __syncthreads();
    const long long* t64 = (const long long*)target;
    for (int i = threadIdx.x; i < 1024; i += 256) {
        long long v = t64[i];
        if (v < 0 || v > 3) atomicOr(&bad, 1);
    }
    for (int i = threadIdx.x; i < LUTN; i += 256)
        g_lut[i] = sqrtf((float)i);
    __syncthreads();
    if (threadIdx.x == 0) {
        g_is64 = bad ? 0 : 1;
        g_count = 0;
        #pragma unroll
        for (int i = 0; i < 8; i++) g_flags[i] = 0;
    }
}

// ---------------------------------------------------------------------------
// Kernel A: fused one-hot init + exact W-EDT (bit-scan on 48-bit line masks)
// + exact H min-plus. One block per (m, d) plane. Writes W+H squared dists
// to g_bufA in (d,h,w) layout.
// ---------------------------------------------------------------------------
__global__ void __launch_bounds__(192) kA(const void* __restrict__ target) {
    __shared__ unsigned char lab[PLANE];
    __shared__ unsigned long long lmask[48];
    __shared__ float s[48][49];
    __shared__ int anyflag;

    const int tid = threadIdx.x;
    const int m = blockIdx.x / 48;
    const int d = blockIdx.x - m * 48;
    const int sign = m >> 3;
    const int b = (m >> 2) & 1;
    const int c = m & 3;

    if (tid < 48) lmask[tid] = 0ULL;
    if (tid == 0) anyflag = 0;

    const int vbase = b * VOL + d * PLANE;
    if (g_is64) {
        const long long* t = (const long long*)target;
        for (int i = tid; i < PLANE; i += 192) lab[i] = (unsigned char)t[vbase + i];
    } else {
        const int* t = (const int*)target;
        for (int i = tid; i < PLANE; i += 192) lab[i] = (unsigned char)t[vbase + i];
    }
    __syncthreads();

    {
        int h = tid >> 2;
        int w0 = (tid & 3) * 12;
        unsigned long long bits = 0ULL;
        int any = 0;
        #pragma unroll
        for (int k = 0; k < 12; k++) {
            int w = w0 + k;
            int isc = (lab[h * 48 + w] == (unsigned char)c);
            any |= isc;
            unsigned long long bin = (unsigned long long)(isc ^ sign);
            bits |= bin << w;
        }
        if (bits) atomicOr(&lmask[h], bits);
        if (any) anyflag = 1;
    }
    __syncthreads();

    if (tid == 0 && sign == 0 && anyflag) atomicOr(&g_flags[b * 4 + c], 1);

    #pragma unroll
    for (int k = 0; k < 12; k++) {
        int i = tid + k * 192;
        int hh = i / 48;
        int ww = i - hh * 48;
        unsigned long long mm = lmask[hh];
        unsigned long long lowm = mm << (63 - ww);
        unsigned long long him  = mm >> ww;
        int dl = lowm ? __clzll(lowm) : 99;
        int dr = him ? (__ffsll(him) - 1) : 99;
        int dd = min(dl, dr);
        float v = (dd <= 47) ? (float)(dd * dd) : INF9;
        s[hh][ww] = v + (float)(hh * hh);
    }
    __syncthreads();

    const int grp = tid & 3;
    const int lane = tid >> 2;
    float acc[12], xv[12];
    #pragma unroll
    for (int k = 0; k < 12; k++) { acc[k] = 1.0e30f; xv[k] = (float)(grp * 12 + k); }

    #pragma unroll
    for (int jc = 0; jc < 4; jc++) {
        float sv[12];
        #pragma unroll
        for (int t = 0; t < 12; t++) sv[t] = s[jc * 12 + t][lane];
        #pragma unroll
        for (int t = 0; t < 12; t++) {
            const float cj = -2.0f * (float)(jc * 12 + t);
            #pragma unroll
            for (int k = 0; k < 12; k++)
                acc[k] = fminf(acc[k], fmaf(cj, xv[k], sv[t]));
        }
    }

    const int base = m * VOL + d * PLANE;
    #pragma unroll
    for (int k = 0; k < 12; k++) {
        int x = grp * 12 + k;
        g_bufA[base + x * 48 + lane] = acc[k] + (float)(x * x);
    }
}

// ---------------------------------------------------------------------------
// Kernel B: exact D min-plus for BOTH signs of one (b,c,h) plane, then store
// the SUM pos^2 + neg^2 (exact |sdf|^2 since one term is always zero).
// 384 threads: half-block per sign. Blocks = 8*48.
// ---------------------------------------------------------------------------
__global__ void __launch_bounds__(384) kB() {
    __shared__ float s[2][48][49];
    __shared__ float o[48][49];

    const int tid = threadIdx.x;
    const int sgn = tid / 192;
    const int t   = tid - sgn * 192;
    const int bc = blockIdx.x / 48;
    const int h  = blockIdx.x - bc * 48;
    const int m  = sgn * 8 + bc;
    const int inbase = m * VOL + h * 48;

    for (int i = t; i < PLANE; i += 192) {
        int dd = i / 48;
        int w = i - dd * 48;
        s[sgn][dd][w] = g_bufA[inbase + dd * PLANE + w] + (float)(dd * dd);
    }
    __syncthreads();

    const int grp = t & 3;
    const int lane = t >> 2;
    float acc[12], xv[12];
    #pragma unroll
    for (int k = 0; k < 12; k++) { acc[k] = 1.0e30f; xv[k] = (float)(grp * 12 + k); }

    #pragma unroll
    for (int jc = 0; jc < 4; jc++) {
        float sv[12];
        #pragma unroll
        for (int tt = 0; tt < 12; tt++) sv[tt] = s[sgn][jc * 12 + tt][lane];
        #pragma unroll
        for (int tt = 0; tt < 12; tt++) {
            const float cj = -2.0f * (float)(jc * 12 + tt);
            #pragma unroll
            for (int k = 0; k < 12; k++)
                acc[k] = fminf(acc[k], fmaf(cj, xv[k], sv[tt]));
        }
    }

    if (sgn == 0) {
        #pragma unroll
        for (int k = 0; k < 12; k++) {
            int x = grp * 12 + k;
            o[x][lane] = acc[k] + (float)(x * x);
        }
    }
    __syncthreads();
    if (sgn == 1) {
        const int outbase = bc * VOL + h * 48;
        #pragma unroll
        for (int k = 0; k < 12; k++) {
            int x = grp * 12 + k;
            g_bufB[outbase + x * PLANE + lane] = o[x][lane] + acc[k] + (float)(x * x);
        }
    }
}

// ---------------------------------------------------------------------------
// Loss: softmax + sum p * sqrt(D2) via LUT; deterministic double partials;
// last block finishes.
// ---------------------------------------------------------------------------
__global__ void __launch_bounds__(256) k_loss(const float* __restrict__ pred,
                                              float* __restrict__ out) {
    double sum = 0.0;
    const int idx = blockIdx.x * blockDim.x + threadIdx.x;
    {
        int b  = idx / VOL;
        int sp = idx - b * VOL;
        int pb = b * 4 * VOL + sp;

        float p0 = pred[pb];
        float p1 = pred[pb + VOL];
        float p2 = pred[pb + 2 * VOL];
        float p3 = pred[pb + 3 * VOL];
        float d0 = g_bufB[pb];
        float d1 = g_bufB[pb + VOL];
        float d2 = g_bufB[pb + 2 * VOL];
        float d3 = g_bufB[pb + 3 * VOL];
        float dv[4] = {d0, d1, d2, d3};

        float mx = fmaxf(fmaxf(p0, p1), fmaxf(p2, p3));
        float e[4];
        e[0] = __expf(p0 - mx);
        e[1] = __expf(p1 - mx);
        e[2] = __expf(p2 - mx);
        e[3] = __expf(p3 - mx);
        float inv = __fdividef(1.0f, e[0] + e[1] + e[2] + e[3]);

        float local = 0.0f;
        #pragma unroll
        for (int c = 0; c < 4; c++) {
            if (g_flags[b * 4 + c]) {
                float v = dv[c];
                float s = (v < (float)LUTN) ? __ldg(&g_lut[(int)v]) : sqrtf(v);
                local += e[c] * s;
            }
        }
        sum = (double)(local * inv);
    }

    __shared__ double sh[256];
    __shared__ int islast;
    sh[threadIdx.x] = sum;
    __syncthreads();
    #pragma unroll
    for (int s = 128; s > 0; s >>= 1) {
        if (threadIdx.x < s) sh[threadIdx.x] += sh[threadIdx.x + s];
        __syncthreads();
    }
    if (threadIdx.x == 0) {
        g_partials[blockIdx.x] = sh[0];
        __threadfence();
        int done = atomicAdd(&g_count, 1);
        islast = (done == gridDim.x - 1);
    }
    __syncthreads();

    if (islast) {
        double v = 0.0;
        for (int i = threadIdx.x; i < LOSSBLKS; i += 256) v += g_partials[i];
        sh[threadIdx.x] = v;
        __syncthreads();
        #pragma unroll
        for (int s = 128; s > 0; s >>= 1) {
            if (threadIdx.x < s) sh[threadIdx.x] += sh[threadIdx.x + s];
            __syncthreads();
        }
        if (threadIdx.x == 0) out[0] = (float)(sh[0] / (double)TOTALE);
    }
}

// ---------------------------------------------------------------------------
extern "C" void kernel_launch(void* const* d_in, const int* in_sizes, int n_in,
                              void* d_out, int out_size) {
    const float* pred   = (const float*)d_in[0];
    const void*  target = d_in[1];
    float* out = (float*)d_out;

    k_detect<<<1, 256>>>(target);
    kA<<<NM * 48, 192>>>(target);    // init + W bit-scan + H min-plus -> g_bufA
    kB<<<8 * 48, 384>>>();           // D min-plus both signs, summed -> g_bufB
    k_loss<<<LOSSBLKS, 256>>>(pred, out);
}

// round 4
// speedup vs baseline: 1.7815x; 1.3882x over previous
#include <cuda_runtime.h>
#include <math.h>

#define VOL    110592   // 48*48*48
#define VOL4   27648    // VOL/4
#define PLANE  2304     // 48*48
#define NVOX   221184   // B * VOL
#define TOTALE 884736   // B*C*VOL
#define INF9   1.0e9f
#define LUTN   6640
#define LOSSBLKS 216    // NVOX / 4 / 256

// Static scratch (no allocations allowed)
__device__ float  g_bufA[8 * VOL];    // pos^2 after W+H per (b,c)
__device__ float  g_bufB[8 * VOL];    // pos^2 after W+H+D per (b,c)
__device__ float  g_lut[LUTN];
__device__ int    g_flags[8];
__device__ int    g_is64;
__device__ int    g_count;
__device__ double g_partials[LOSSBLKS];

// ---------------------------------------------------------------------------
// Detect target dtype (int64 vs int32); zero flags/counter; build sqrt LUT.
// ---------------------------------------------------------------------------
__global__ void k_detect(const void* __restrict__ target) {
    __shared__ int bad;
    if (threadIdx.x == 0) bad = 0;
    __syncthreads();
    const long long* t64 = (const long long*)target;
    for (int i = threadIdx.x; i < 1024; i += 256) {
        long long v = t64[i];
        if (v < 0 || v > 3) atomicOr(&bad, 1);
    }
    for (int i = threadIdx.x; i < LUTN; i += 256)
        g_lut[i] = sqrtf((float)i);
    __syncthreads();
    if (threadIdx.x == 0) {
        g_is64 = bad ? 0 : 1;
        g_count = 0;
        #pragma unroll
        for (int i = 0; i < 8; i++) g_flags[i] = 0;
    }
}

// ---------------------------------------------------------------------------
// Kernel A: fused one-hot init + exact W-EDT (bit-scan on 48-bit line masks)
// + exact H min-plus, POS masks only (neg recovered later via class-min).
// One block per (m=b*4+c, d) plane. Writes W+H squared dists to g_bufA.
// ---------------------------------------------------------------------------
__global__ void __launch_bounds__(192) kA(const void* __restrict__ target) {
    __shared__ unsigned char lab[PLANE];
    __shared__ unsigned long long lmask[48];
    __shared__ float s[48][49];
    __shared__ int anyflag;

    const int tid = threadIdx.x;
    const int m = blockIdx.x / 48;         // m in [0,8): b*4 + c
    const int d = blockIdx.x - m * 48;
    const int b = m >> 2;
    const int c = m & 3;

    if (tid < 48) lmask[tid] = 0ULL;
    if (tid == 0) anyflag = 0;

    const int vbase = b * VOL + d * PLANE;
    if (g_is64) {
        const long long* t = (const long long*)target;
        for (int i = tid; i < PLANE; i += 192) lab[i] = (unsigned char)t[vbase + i];
    } else {
        const int* t = (const int*)target;
        for (int i = tid; i < PLANE; i += 192) lab[i] = (unsigned char)t[vbase + i];
    }
    __syncthreads();

    // Build per-line seed bitmasks.
    {
        int h = tid >> 2;
        int w0 = (tid & 3) * 12;
        unsigned long long bits = 0ULL;
        #pragma unroll
        for (int k = 0; k < 12; k++) {
            int w = w0 + k;
            unsigned long long isc =
                (unsigned long long)(lab[h * 48 + w] == (unsigned char)c);
            bits |= isc << w;
        }
        if (bits) { atomicOr(&lmask[h], bits); anyflag = 1; }
    }
    __syncthreads();

    if (tid == 0 && anyflag) atomicOr(&g_flags[m], 1);

    // Exact W distances via clz/ffs; fold +h^2 for the H pass.
    #pragma unroll
    for (int k = 0; k < 12; k++) {
        int i = tid + k * 192;
        int hh = i / 48;
        int ww = i - hh * 48;
        unsigned long long mm = lmask[hh];
        unsigned long long lowm = mm << (63 - ww);
        unsigned long long him  = mm >> ww;
        int dl = lowm ? __clzll(lowm) : 99;
        int dr = him ? (__ffsll(him) - 1) : 99;
        int dd = min(dl, dr);
        float v = (dd <= 47) ? (float)(dd * dd) : INF9;
        s[hh][ww] = v + (float)(hh * hh);
    }
    __syncthreads();

    // H min-plus: grp owns 12 outputs x; lane = w.
    const int grp = tid & 3;
    const int lane = tid >> 2;
    float acc[12], xv[12];
    #pragma unroll
    for (int k = 0; k < 12; k++) { acc[k] = 1.0e30f; xv[k] = (float)(grp * 12 + k); }

    #pragma unroll
    for (int jc = 0; jc < 4; jc++) {
        float sv[12];
        #pragma unroll
        for (int t = 0; t < 12; t++) sv[t] = s[jc * 12 + t][lane];
        #pragma unroll
        for (int t = 0; t < 12; t++) {
            const float cj = -2.0f * (float)(jc * 12 + t);
            #pragma unroll
            for (int k = 0; k < 12; k++)
                acc[k] = fminf(acc[k], fmaf(cj, xv[k], sv[t]));
        }
    }

    const int base = m * VOL + d * PLANE;
    #pragma unroll
    for (int k = 0; k < 12; k++) {
        int x = grp * 12 + k;
        g_bufA[base + x * 48 + lane] = acc[k] + (float)(x * x);
    }
}

// ---------------------------------------------------------------------------
// Kernel B: exact D min-plus, pos only. One block per (m, h) plane (d, w).
// ---------------------------------------------------------------------------
__global__ void __launch_bounds__(192) kB() {
    __shared__ float s[48][49];
    const int tid = threadIdx.x;
    const int m = blockIdx.x / 48;
    const int h = blockIdx.x - m * 48;
    const int base = m * VOL + h * 48;

    for (int i = tid; i < PLANE; i += 192) {
        int dd = i / 48;
        int w = i - dd * 48;
        s[dd][w] = g_bufA[base + dd * PLANE + w] + (float)(dd * dd);
    }
    __syncthreads();

    const int grp = tid & 3;
    const int lane = tid >> 2;
    float acc[12], xv[12];
    #pragma unroll
    for (int k = 0; k < 12; k++) { acc[k] = 1.0e30f; xv[k] = (float)(grp * 12 + k); }

    #pragma unroll
    for (int jc = 0; jc < 4; jc++) {
        float sv[12];
        #pragma unroll
        for (int t = 0; t < 12; t++) sv[t] = s[jc * 12 + t][lane];
        #pragma unroll
        for (int t = 0; t < 12; t++) {
            const float cj = -2.0f * (float)(jc * 12 + t);
            #pragma unroll
            for (int k = 0; k < 12; k++)
                acc[k] = fminf(acc[k], fmaf(cj, xv[k], sv[t]));
        }
    }

    #pragma unroll
    for (int k = 0; k < 12; k++) {
        int x = grp * 12 + k;
        g_bufB[base + x * PLANE + lane] = acc[k] + (float)(x * x);
    }
}

// ---------------------------------------------------------------------------
// Loss: 4 voxels/thread, float4 front-batched loads (MLP=8), softmax,
// neg^2 = min of other classes' pos^2 (exact: classes partition the volume),
// |sdf| = sqrt(pos^2 + neg^2) via LUT. Deterministic double reduction,
// last-block-finishes.
// ---------------------------------------------------------------------------
__global__ void __launch_bounds__(256) k_loss(const float* __restrict__ pred,
                                              float* __restrict__ out) {
    const int t = blockIdx.x * blockDim.x + threadIdx.x;   // 0..55295
    const int b = t / VOL4;
    const int spq = t - b * VOL4;
    const int pb = b * 4 * VOL4 + spq;

    const float4* pred4 = (const float4*)pred;
    const float4* dist4 = (const float4*)g_bufB;

    float4 P[4], D[4];
    #pragma unroll
    for (int c = 0; c < 4; c++) P[c] = __ldg(&pred4[pb + c * VOL4]);
    #pragma unroll
    for (int c = 0; c < 4; c++) D[c] = __ldg(&dist4[pb + c * VOL4]);

    int fl[4];
    #pragma unroll
    for (int c = 0; c < 4; c++) fl[c] = g_flags[b * 4 + c];

    double sum = 0.0;
    #pragma unroll
    for (int v = 0; v < 4; v++) {
        float p0 = ((const float*)&P[0])[v];
        float p1 = ((const float*)&P[1])[v];
        float p2 = ((const float*)&P[2])[v];
        float p3 = ((const float*)&P[3])[v];
        float d0 = ((const float*)&D[0])[v];
        float d1 = ((const float*)&D[1])[v];
        float d2 = ((const float*)&D[2])[v];
        float d3 = ((const float*)&D[3])[v];

        float mx = fmaxf(fmaxf(p0, p1), fmaxf(p2, p3));
        float e0 = __expf(p0 - mx);
        float e1 = __expf(p1 - mx);
        float e2 = __expf(p2 - mx);
        float e3 = __expf(p3 - mx);
        float inv = __fdividef(1.0f, e0 + e1 + e2 + e3);

        // neg^2 per class = min of the other classes' pos^2
        float m01 = fminf(d0, d1), m23 = fminf(d2, d3);
        float tot[4];
        tot[0] = d0 + fminf(d1, m23);
        tot[1] = d1 + fminf(d0, m23);
        tot[2] = d2 + fminf(m01, d3);
        tot[3] = d3 + fminf(m01, d2);
        float e[4] = {e0, e1, e2, e3};

        float local = 0.0f;
        #pragma unroll
        for (int c = 0; c < 4; c++) {
            if (fl[c]) {
                float vv = tot[c];
                float s = (vv < (float)LUTN) ? __ldg(&g_lut[(int)vv]) : sqrtf(vv);
                local += e[c] * s;
            }
        }
        sum += (double)(local * inv);
    }

    __shared__ double sh[256];
    __shared__ int islast;
    sh[threadIdx.x] = sum;
    __syncthreads();
    #pragma unroll
    for (int s = 128; s > 0; s >>= 1) {
        if (threadIdx.x < s) sh[threadIdx.x] += sh[threadIdx.x + s];
        __syncthreads();
    }
    if (threadIdx.x == 0) {
        g_partials[blockIdx.x] = sh[0];
        __threadfence();
        int done = atomicAdd(&g_count, 1);
        islast = (done == gridDim.x - 1);
    }
    __syncthreads();

    if (islast) {
        double v = (threadIdx.x < LOSSBLKS) ? g_partials[threadIdx.x] : 0.0;
        sh[threadIdx.x] = v;
        __syncthreads();
        #pragma unroll
        for (int s = 128; s > 0; s >>= 1) {
            if (threadIdx.x < s) sh[threadIdx.x] += sh[threadIdx.x + s];
            __syncthreads();
        }
        if (threadIdx.x == 0) out[0] = (float)(sh[0] / (double)TOTALE);
    }
}

// ---------------------------------------------------------------------------
extern "C" void kernel_launch(void* const* d_in, const int* in_sizes, int n_in,
                              void* d_out, int out_size) {
    const float* pred   = (const float*)d_in[0];
    const void*  target = d_in[1];
    float* out = (float*)d_out;

    k_detect<<<1, 256>>>(target);
    kA<<<8 * 48, 192>>>(target);    // init + W bit-scan + H min-plus -> g_bufA
    kB<<<8 * 48, 192>>>();          // D min-plus -> g_bufB (pos^2 only)
    k_loss<<<LOSSBLKS, 256>>>(pred, out);
}

// round 6
// speedup vs baseline: 1.7961x; 1.0082x over previous
#include <cuda_runtime.h>
#include <math.h>

#define VOL    110592   // 48*48*48
#define PLANE  2304     // 48*48
#define NVOX   221184   // B * VOL
#define TOTALE 884736   // B*C*VOL
#define INF9   1.0e9f
#define LUTN   6640
#define NBLK   96       // B(2) * 48

// Static scratch (no allocations allowed)
__device__ float  g_bufA[8 * VOL];    // pos^2 after W+H per (b,c)
__device__ float  g_lut[LUTN];
__device__ int    g_flags[8];         // zero-initialized; reset by kB epilogue
__device__ int    g_count;            // zero-initialized; reset by kB epilogue
__device__ double g_partials[NBLK];

// ---------------------------------------------------------------------------
// Kernel A: one block per (b,d) plane, 768 threads = 4 class-groups of 192.
// Self-detects target dtype, loads labels ONCE, builds per-class line masks,
// exact W-EDT via clz/ffs, exact H min-plus. Block 0 also (re)builds the LUT.
// Writes W+H squared distances to g_bufA[(b*4+c)*VOL + d*PLANE + h*48 + w].
// ---------------------------------------------------------------------------
__global__ void __launch_bounds__(768) kA(const void* __restrict__ target) {
    __shared__ unsigned char lab[PLANE];
    __shared__ unsigned long long lmask[4][48];
    __shared__ float s[4][48][49];
    __shared__ int sbad;
    __shared__ int anyf[4];

    const int tid = threadIdx.x;
    const int bd = blockIdx.x;
    const int b = bd / 48;
    const int d = bd - b * 48;
    const int cgrp = tid / 192;       // class
    const int t = tid - cgrp * 192;

    if (tid == 0) sbad = 0;
    if (tid < 4) anyf[tid] = 0;
    if (tid < 192) ((unsigned long long*)lmask)[tid] = 0ULL;
    __syncthreads();

    // dtype detection from the first 512 bytes (in-bounds for both dtypes).
    if (tid < 64) {
        long long v = ((const long long*)target)[tid];
        if (v < 0 || v > 3) atomicOr(&sbad, 1);
    }
    __syncthreads();
    const bool is64 = (sbad == 0);

    // Load this (b,d) plane's labels once.
    const int vbase = b * VOL + d * PLANE;
    if (is64) {
        const long long* tp = (const long long*)target;
        for (int i = tid; i < PLANE; i += 768) lab[i] = (unsigned char)tp[vbase + i];
    } else {
        const int* tp = (const int*)target;
        for (int i = tid; i < PLANE; i += 768) lab[i] = (unsigned char)tp[vbase + i];
    }
    __syncthreads();

    // Per-class line masks.
    {
        int h = t >> 2;
        int w0 = (t & 3) * 12;
        unsigned long long bits = 0ULL;
        #pragma unroll
        for (int k = 0; k < 12; k++) {
            int w = w0 + k;
            unsigned long long isc =
                (unsigned long long)(lab[h * 48 + w] == (unsigned char)cgrp);
            bits |= isc << w;
        }
        if (bits) { atomicOr(&lmask[cgrp][h], bits); anyf[cgrp] = 1; }
    }
    __syncthreads();
    if (t == 0 && anyf[cgrp]) atomicOr(&g_flags[b * 4 + cgrp], 1);

    // Block 0 rebuilds sqrt LUT (consumed by kB later in the stream).
    if (bd == 0) {
        for (int i = tid; i < LUTN; i += 768) g_lut[i] = sqrtf((float)i);
    }

    // Exact W distances via clz/ffs; fold +h^2 for the H pass.
    #pragma unroll
    for (int k = 0; k < 12; k++) {
        int i = t + k * 192;
        int hh = i / 48;
        int ww = i - hh * 48;
        unsigned long long mm = lmask[cgrp][hh];
        unsigned long long lowm = mm << (63 - ww);
        unsigned long long him  = mm >> ww;
        int dl = lowm ? __clzll(lowm) : 99;
        int dr = him ? (__ffsll(him) - 1) : 99;
        int dd = min(dl, dr);
        float v = (dd <= 47) ? (float)(dd * dd) : INF9;
        s[cgrp][hh][ww] = v + (float)(hh * hh);
    }
    __syncthreads();

    // H min-plus: within group, grp owns 12 outputs x; lane = w.
    const int grp = t & 3;
    const int lane = t >> 2;
    float acc[12], xv[12];
    #pragma unroll
    for (int k = 0; k < 12; k++) { acc[k] = 1.0e30f; xv[k] = (float)(grp * 12 + k); }

    #pragma unroll
    for (int jc = 0; jc < 4; jc++) {
        float sv[12];
        #pragma unroll
        for (int tt = 0; tt < 12; tt++) sv[tt] = s[cgrp][jc * 12 + tt][lane];
        #pragma unroll
        for (int tt = 0; tt < 12; tt++) {
            const float cj = -2.0f * (float)(jc * 12 + tt);
            #pragma unroll
            for (int k = 0; k < 12; k++)
                acc[k] = fminf(acc[k], fmaf(cj, xv[k], sv[tt]));
        }
    }

    const int base = (b * 4 + cgrp) * VOL + d * PLANE;
    #pragma unroll
    for (int k = 0; k < 12; k++) {
        int x = grp * 12 + k;
        g_bufA[base + x * 48 + lane] = acc[k] + (float)(x * x);
    }
}

// ---------------------------------------------------------------------------
// Kernel B: one block per (b,h) plane, 768 threads = 4 class-groups of 192.
// Exact D min-plus for all 4 classes into shared, then fused loss:
// softmax(pred) dot sqrt(pos^2 + min-over-other-classes pos^2), LUT sqrt.
// Deterministic double reduction (768 = 3*256 handled explicitly);
// last block finishes and resets globals for the next graph replay.
// ---------------------------------------------------------------------------
__global__ void __launch_bounds__(768) kB(const float* __restrict__ pred,
                                          float* __restrict__ out) {
    __shared__ float s[4][48][49];
    __shared__ double sh[768];
    __shared__ int islast;

    const int tid = threadIdx.x;
    const int bh = blockIdx.x;
    const int b = bh / 48;
    const int h = bh - b * 48;
    const int cgrp = tid / 192;
    const int t = tid - cgrp * 192;
    const int base = (b * 4 + cgrp) * VOL + h * 48;

    for (int i = t; i < PLANE; i += 192) {
        int dd = i / 48;
        int w = i - dd * 48;
        s[cgrp][dd][w] = g_bufA[base + dd * PLANE + w] + (float)(dd * dd);
    }
    __syncthreads();

    const int grp = t & 3;
    const int lane = t >> 2;
    float acc[12], xv[12];
    #pragma unroll
    for (int k = 0; k < 12; k++) { acc[k] = 1.0e30f; xv[k] = (float)(grp * 12 + k); }

    #pragma unroll
    for (int jc = 0; jc < 4; jc++) {
        float sv[12];
        #pragma unroll
        for (int tt = 0; tt < 12; tt++) sv[tt] = s[cgrp][jc * 12 + tt][lane];
        #pragma unroll
        for (int tt = 0; tt < 12; tt++) {
            const float cj = -2.0f * (float)(jc * 12 + tt);
            #pragma unroll
            for (int k = 0; k < 12; k++)
                acc[k] = fminf(acc[k], fmaf(cj, xv[k], sv[tt]));
        }
    }
    __syncthreads();   // everyone finished reading s

    // Write final squared distances (+x^2) back into s (reuse).
    #pragma unroll
    for (int k = 0; k < 12; k++) {
        int x = grp * 12 + k;
        s[cgrp][x][lane] = acc[k] + (float)(x * x);
    }
    __syncthreads();

    // ---- fused loss over this (b,h) plane: 3 voxels/thread ----
    int fl[4];
    #pragma unroll
    for (int c = 0; c < 4; c++) fl[c] = g_flags[b * 4 + c];

    const float* pp = pred + b * 4 * VOL + h * 48;
    double sum = 0.0;
    #pragma unroll
    for (int k = 0; k < 3; k++) {
        int i = tid + k * 768;         // plane index: d*48 + w
        int dd = i / 48;
        int w = i - dd * 48;
        int off = dd * PLANE + w;

        float p0 = __ldg(&pp[off]);
        float p1 = __ldg(&pp[off + VOL]);
        float p2 = __ldg(&pp[off + 2 * VOL]);
        float p3 = __ldg(&pp[off + 3 * VOL]);
        float d0 = s[0][dd][w];
        float d1 = s[1][dd][w];
        float d2 = s[2][dd][w];
        float d3 = s[3][dd][w];

        float mx = fmaxf(fmaxf(p0, p1), fmaxf(p2, p3));
        float e[4];
        e[0] = __expf(p0 - mx);
        e[1] = __expf(p1 - mx);
        e[2] = __expf(p2 - mx);
        e[3] = __expf(p3 - mx);
        float inv = __fdividef(1.0f, e[0] + e[1] + e[2] + e[3]);

        float m01 = fminf(d0, d1), m23 = fminf(d2, d3);
        float tot[4];
        tot[0] = d0 + fminf(d1, m23);
        tot[1] = d1 + fminf(d0, m23);
        tot[2] = d2 + fminf(m01, d3);
        tot[3] = d3 + fminf(m01, d2);

        float local = 0.0f;
        #pragma unroll
        for (int c = 0; c < 4; c++) {
            if (fl[c]) {
                float vv = tot[c];
                float sq = (vv < (float)LUTN) ? __ldg(&g_lut[(int)vv]) : sqrtf(vv);
                local += e[c] * sq;
            }
        }
        sum += (double)(local * inv);
    }

    // ---- deterministic block reduction: 768 -> 256 (3-way) -> tree ----
    sh[tid] = sum;
    __syncthreads();
    if (tid < 256) sh[tid] += sh[tid + 256] + sh[tid + 512];
    __syncthreads();
    #pragma unroll
    for (int st = 128; st > 0; st >>= 1) {
        if (tid < st) sh[tid] += sh[tid + st];
        __syncthreads();
    }
    if (tid == 0) {
        g_partials[bh] = sh[0];
        __threadfence();
        int done = atomicAdd(&g_count, 1);
        islast = (done == NBLK - 1);
    }
    __syncthreads();

    if (islast) {
        double v = (tid < NBLK) ? g_partials[tid] : 0.0;   // NBLK=96 < 128
        sh[tid] = v;
        __syncthreads();
        #pragma unroll
        for (int st = 64; st > 0; st >>= 1) {              // 96 <= 128: pairs 0..63 cover 64..127(=0 pad ok: 96..127 are 0)
            if (tid < st) sh[tid] += sh[tid + st];
            __syncthreads();
        }
        if (tid == 0) {
            out[0] = (float)(sh[0] / (double)TOTALE);
            g_count = 0;                    // reset for next graph replay
        }
        if (tid < 8) g_flags[tid] = 0;      // reset for next graph replay
    }
}

// ---------------------------------------------------------------------------
extern "C" void kernel_launch(void* const* d_in, const int* in_sizes, int n_in,
                              void* d_out, int out_size) {
    const float* pred   = (const float*)d_in[0];
    const void*  target = d_in[1];
    float* out = (float*)d_out;

    kA<<<NBLK, 768>>>(target);          // labels -> W bit-scan + H min-plus
    kB<<<NBLK, 768>>>(pred, out);       // D min-plus + fused loss + reduce
}